// round 17
// baseline (speedup 1.0000x reference)
#include <cuda_runtime.h>
#include <cuda_bf16.h>
#include <math.h>

// AUCM pairwise margin loss, B=1024, C=128, margin=1. One launch.
//
// Math: softplus(b-a), a,b = sigmoids in (0,1), t = b-a in (-1,1):
//   softplus(t) = ln2 + t/2 + t^2/8 - t^4/192   (degree-4; ~1.5e-5 realistic
//   truncation, gate is 1e-3)
// Binomial factorization collapses the O(B^2) (pos,neg) pair sum per class
// to power sums: T_k over all rows (T_0 = 1024 free), P_k over pos rows.
//
// R17 = champion structure (128 blocks x 128 threads, block-local classes,
// HW-tanh sigmoid, ballot P0, packed 64-bit atomic tail) + forced full
// front-batching of the 16 loads (two pure-load unrolled loops, compute
// strictly after) to push per-thread MLP_eff toward 16 (R16 showed regs=31,
// i.e. ptxas had re-waved the loads into smaller batches).
//
// Frozen by measurement: threads 64/128/256 -> 7.97/6.30/6.66 us; four
// cross-block exchange topologies (global-atomic x2, STG/reload, DSMEM)
// all slower than block-local; instruction micro-cuts sub-noise.

#define NROWS 1024
#define NCLS  128
#define NBLK  128
#define NTH   128
#define NW    (NTH / 32)     // 4 warps
#define RPT   (NROWS / NTH)  // 8 rows per thread
#define FXS   1099511627776.0   // 2^40 fixed-point scale

__device__ unsigned long long g_pack = 0ULL;

__device__ __forceinline__ float fast_sigmoid(float x) {
    float th;
    asm("tanh.approx.f32 %0, %1;" : "=f"(th) : "f"(0.5f * x));
    return fmaf(0.5f, th, 0.5f);
}

__global__ __launch_bounds__(NTH)
void aucm_kernel(const float* __restrict__ logits,
                 const float* __restrict__ targets,
                 float* __restrict__ out)
{
    const int c    = blockIdx.x;   // class
    const int tid  = threadIdx.x;
    const int warp = tid >> 5;
    const int lane = tid & 31;

    // Forced front-batch: two pure-load loops, 16 LDGs issued before any
    // dependent compute. Arrays fully live -> MLP_eff ~ 16.
    float xs[RPT], tg[RPT];
#pragma unroll
    for (int r = 0; r < RPT; r++)
        xs[r] = logits [(tid + r * NTH) * NCLS + c];
#pragma unroll
    for (int r = 0; r < RPT; r++)
        tg[r] = targets[(tid + r * NTH) * NCLS + c];   // exact 0.0f / 1.0f

    // Power sums: T_k over my rows (k=1..4), P_k over pos rows (k=1..4);
    // P0 as an exact warp-uniform popcount.
    float T1 = 0.f, T2 = 0.f, T3 = 0.f, T4 = 0.f;
    float P1 = 0.f, P2 = 0.f, P3 = 0.f, P4 = 0.f;
    int   np = 0;   // warp-total (uniform across lanes)
#pragma unroll
    for (int r = 0; r < RPT; r++) {
        const float p  = fast_sigmoid(xs[r]);
        const float p2 = p * p, p3 = p2 * p, p4 = p2 * p2;
        T1 += p; T2 += p2; T3 += p3; T4 += p4;
        const float t = tg[r];
        np += __popc(__ballot_sync(0xffffffffu, t > 0.5f));
        P1 = fmaf(t, p,  P1);
        P2 = fmaf(t, p2, P2);
        P3 = fmaf(t, p3, P3);
        P4 = fmaf(t, p4, P4);
    }

    // Warp tree reduction (8 float accumulators; np already warp-uniform).
#pragma unroll
    for (int off = 16; off > 0; off >>= 1) {
        T1 += __shfl_xor_sync(0xffffffffu, T1, off);
        T2 += __shfl_xor_sync(0xffffffffu, T2, off);
        T3 += __shfl_xor_sync(0xffffffffu, T3, off);
        T4 += __shfl_xor_sync(0xffffffffu, T4, off);
        P1 += __shfl_xor_sync(0xffffffffu, P1, off);
        P2 += __shfl_xor_sync(0xffffffffu, P2, off);
        P3 += __shfl_xor_sync(0xffffffffu, P3, off);
        P4 += __shfl_xor_sync(0xffffffffu, P4, off);
    }

    __shared__ float s[NW][8];
    __shared__ int   sn[NW];
    if (lane == 0) {
        s[warp][0] = T1; s[warp][1] = T2; s[warp][2] = T3; s[warp][3] = T4;
        s[warp][4] = P1; s[warp][5] = P2; s[warp][6] = P3; s[warp][7] = P4;
        sn[warp] = np;
    }
    __syncthreads();
    if (tid != 0) return;

    // ---- thread 0: cross-warp sum (32 pipelined LDS) + fp32 combine ----
    float m[8];
#pragma unroll
    for (int k = 0; k < 8; k++)
        m[k] = (s[0][k] + s[1][k]) + (s[2][k] + s[3][k]);
    const int npos = (sn[0] + sn[1]) + (sn[2] + sn[3]);

    const float Pd0 = (float)npos;
    const float Td1 = m[0], Td2 = m[1], Td3 = m[2], Td4 = m[3];
    const float Pd1 = m[4], Pd2 = m[5], Pd3 = m[6], Pd4 = m[7];
    const float B0 = (float)(NROWS - npos);
    const float B1 = Td1 - Pd1, B2 = Td2 - Pd2,
                B3 = Td3 - Pd3, B4 = Td4 - Pd4;   // neg-row power sums

    const float cnt = Pd0 * B0;
    // d_m = sum_pairs (b-a)^m via binomial; signs from (-a)^k.
    const float d1 = B1 * Pd0 - B0 * Pd1;
    const float d2 = B2 * Pd0 - 2.0f * B1 * Pd1 + B0 * Pd2;
    const float d4 = B4 * Pd0 - 4.0f * B3 * Pd1 + 6.0f * B2 * Pd2
                   - 4.0f * B1 * Pd3 + B0 * Pd4;

    const float S = 0.69314718f * cnt
                  + 0.5f * d1
                  + d2 * (1.0f / 8.0f)
                  - d4 * (1.0f / 192.0f);

    const bool ok = (cnt > 0.0f);
    const float mean = ok ? (S / cnt) : 0.0f;   // in (0, 1.32)

    // Packed contribution: [count:8][valid:8][mean fixed-point 2^40:48].
    const unsigned long long fx =
        (unsigned long long)((double)mean * FXS + 0.5);
    const unsigned long long pk =
        (1ULL << 56) | ((ok ? 1ULL : 0ULL) << 48) | fx;

    const unsigned long long old = atomicAdd(&g_pack, pk);
    if ((old >> 56) == (unsigned long long)(NBLK - 1)) {
        // Last arriver: total is in hand, no fence/reload needed.
        const unsigned long long tot = old + pk;
        const double sum = (double)(tot & ((1ULL << 48) - 1)) * (1.0 / FXS);
        const double vc  = (double)((tot >> 48) & 0xFFULL);
        out[0] = (vc > 0.0) ? (float)(sum / vc) : 0.0f;
        g_pack = 0ULL;   // reset for next graph replay (all blocks done)
    }
}

extern "C" void kernel_launch(void* const* d_in, const int* in_sizes, int n_in,
                              void* d_out, int out_size)
{
    const float* logits  = (const float*)d_in[0];
    const float* targets = (const float*)d_in[1];
    float* out = (float*)d_out;

    aucm_kernel<<<NBLK, NTH>>>(logits, targets, out);
}